// round 3
// baseline (speedup 1.0000x reference)
#include <cuda_runtime.h>
#include <cstdint>
#include <math.h>

// ---------------------------------------------------------------------------
// GCN: out = softmax( L3 @ W_out + b ),  L_k = relu(AG @ (L_{k-1} @ W_k)) [*drop]
// AG = D^{-1/2}(A+I)D^{-1/2}.  Refactor: AG @ (H W) = D·(A·U + U), U = D·(H W).
// Big GEMM is raw adj @ U with fused epilogue (d-scale, +U, relu, dropout).
// ---------------------------------------------------------------------------

#define NROWS 8192
#define HID   256
#define OUTC  40

// 1 = JAX threefry_partitionable (modern default), 0 = legacy split-iota path
#define DROPOUT_PARTITIONABLE 1

// ------------------------------- scratch -----------------------------------
__device__ float g_d[NROWS];
__device__ float g_xpad[NROWS * 512];
__device__ float g_wpad[512 * 256];
__device__ float g_bufU[NROWS * HID];
__device__ float g_bufH[NROWS * HID];

// ------------------------------ threefry -----------------------------------
__host__ __device__ __forceinline__ void threefry2x32(
    unsigned k0, unsigned k1, unsigned x0, unsigned x1,
    unsigned &o0, unsigned &o1)
{
    unsigned ks2 = k0 ^ k1 ^ 0x1BD11BDAu;
    x0 += k0; x1 += k1;
#define TF_R(r) { x0 += x1; x1 = (x1 << (r)) | (x1 >> (32 - (r))); x1 ^= x0; }
    TF_R(13) TF_R(15) TF_R(26) TF_R(6)
    x0 += k1;  x1 += ks2 + 1u;
    TF_R(17) TF_R(29) TF_R(16) TF_R(24)
    x0 += ks2; x1 += k0 + 2u;
    TF_R(13) TF_R(15) TF_R(26) TF_R(6)
    x0 += k0;  x1 += k1 + 3u;
    TF_R(17) TF_R(29) TF_R(16) TF_R(24)
    x0 += k1;  x1 += ks2 + 4u;
    TF_R(13) TF_R(15) TF_R(26) TF_R(6)
    x0 += ks2; x1 += k0 + 5u;
#undef TF_R
    o0 = x0; o1 = x1;
}

__device__ __forceinline__ float drop_apply(float v, unsigned idx,
                                            unsigned fk0, unsigned fk1)
{
    unsigned o0, o1, bits;
#if DROPOUT_PARTITIONABLE
    threefry2x32(fk0, fk1, 0u, idx, o0, o1);
    bits = o0 ^ o1;
#else
    const unsigned half = (NROWS * HID) / 2u;
    bool lo = idx < half;
    unsigned j = lo ? idx : idx - half;
    threefry2x32(fk0, fk1, j, j + half, o0, o1);
    bits = lo ? o0 : o1;
#endif
    float u = __uint_as_float((bits >> 9) | 0x3f800000u) - 1.0f;
    return (u < 0.7f) ? v / 0.7f : 0.0f;
}

// ------------------------------- helpers -----------------------------------
__device__ __forceinline__ uint32_t f2tf(float f)
{
    uint32_t u;
    asm("cvt.rna.tf32.f32 %0, %1;" : "=r"(u) : "f"(f));
    return u;
}

__device__ __forceinline__ void mma_tf32(float *c, const uint32_t *a, const uint32_t *b)
{
    asm volatile(
        "mma.sync.aligned.m16n8k8.row.col.f32.tf32.tf32.f32 "
        "{%0,%1,%2,%3}, {%4,%5,%6,%7}, {%8,%9}, {%0,%1,%2,%3};\n"
        : "+f"(c[0]), "+f"(c[1]), "+f"(c[2]), "+f"(c[3])
        : "r"(a[0]), "r"(a[1]), "r"(a[2]), "r"(a[3]), "r"(b[0]), "r"(b[1]));
}

// ------------------------------ GEMM core ----------------------------------
// C[8192,256] = A[8192,K] @ B[K,256], tile 64x256x16, 256 threads (8 warps).
// EPI==0: C = acc * d[row]
// EPI==1: v = relu(d[row]*(acc + U[row,col])); optional dropout; C = v
#define A_STRIDE 20
#define B_STRIDE 264

template <int EPI>
__global__ void __launch_bounds__(256, 1) gemm_tf32(
    const float *__restrict__ A, int lda,
    const float *__restrict__ B,          // ldb = 256
    float *__restrict__ C,                // ldc = 256
    int K,
    const float *__restrict__ dv,
    const float *__restrict__ U,
    int doDrop, unsigned fk0, unsigned fk1)
{
    __shared__ float sA[2][64 * A_STRIDE];
    __shared__ float sB[2][16 * B_STRIDE];

    const int tid = threadIdx.x;
    const int m0 = blockIdx.x * 64;
    const int warp = tid >> 5, lane = tid & 31;
    const int wm = warp & 1, wn = warp >> 1;     // 2 x 4 warp grid
    const int lr = lane >> 2, lc = lane & 3;     // groupID / tid-in-group

    // global->reg staging layout
    const int arow = tid >> 2, acol = (tid & 3) << 2;
    int brow[4], bcol[4];
#pragma unroll
    for (int i = 0; i < 4; i++) {
        int idx = i * 256 + tid;
        brow[i] = idx >> 6;
        bcol[i] = (idx & 63) << 2;
    }
    const float *Aptr = A + (size_t)(m0 + arow) * lda + acol;

    float acc[2][8][4];
#pragma unroll
    for (int mi = 0; mi < 2; mi++)
#pragma unroll
        for (int ni = 0; ni < 8; ni++)
#pragma unroll
            for (int q = 0; q < 4; q++) acc[mi][ni][q] = 0.0f;

    const int KT = K / 16;
    float4 aR, bR[4];

    // prologue: tile 0
    aR = __ldcs((const float4 *)(Aptr));
#pragma unroll
    for (int i = 0; i < 4; i++)
        bR[i] = __ldg((const float4 *)(B + (size_t)brow[i] * 256 + bcol[i]));
    {
        float *dA = sA[0] + arow * A_STRIDE + acol;
        dA[0] = aR.x; dA[1] = aR.y; dA[2] = aR.z; dA[3] = aR.w;
#pragma unroll
        for (int i = 0; i < 4; i++) {
            float *dB = sB[0] + brow[i] * B_STRIDE + bcol[i];
            dB[0] = bR[i].x; dB[1] = bR[i].y; dB[2] = bR[i].z; dB[3] = bR[i].w;
        }
    }
    __syncthreads();

    for (int kt = 0; kt < KT; kt++) {
        const int cur = kt & 1;
        if (kt + 1 < KT) {
            aR = __ldcs((const float4 *)(Aptr + (size_t)(kt + 1) * 16));
#pragma unroll
            for (int i = 0; i < 4; i++)
                bR[i] = __ldg((const float4 *)(B + (size_t)((kt + 1) * 16 + brow[i]) * 256 + bcol[i]));
        }

        // ---- compute current tile ----
        const float *As = sA[cur];
        const float *Bs = sB[cur];
#pragma unroll
        for (int ks = 0; ks < 2; ks++) {
            const int kb = ks * 8;
            uint32_t bf[8][2];
#pragma unroll
            for (int ni = 0; ni < 8; ni++) {
                int col = wn * 64 + ni * 8 + lr;
                bf[ni][0] = f2tf(Bs[(kb + lc) * B_STRIDE + col]);
                bf[ni][1] = f2tf(Bs[(kb + lc + 4) * B_STRIDE + col]);
            }
            uint32_t af[2][4];
#pragma unroll
            for (int mi = 0; mi < 2; mi++) {
                int r0 = wm * 32 + mi * 16 + lr;
                af[mi][0] = f2tf(As[r0 * A_STRIDE + kb + lc]);
                af[mi][1] = f2tf(As[(r0 + 8) * A_STRIDE + kb + lc]);
                af[mi][2] = f2tf(As[r0 * A_STRIDE + kb + lc + 4]);
                af[mi][3] = f2tf(As[(r0 + 8) * A_STRIDE + kb + lc + 4]);
            }
#pragma unroll
            for (int mi = 0; mi < 2; mi++)
#pragma unroll
                for (int ni = 0; ni < 8; ni++)
                    mma_tf32(acc[mi][ni], af[mi], bf[ni]);
        }

        if (kt + 1 < KT) {
            const int nxt = cur ^ 1;
            float *dA = sA[nxt] + arow * A_STRIDE + acol;
            dA[0] = aR.x; dA[1] = aR.y; dA[2] = aR.z; dA[3] = aR.w;
#pragma unroll
            for (int i = 0; i < 4; i++) {
                float *dB = sB[nxt] + brow[i] * B_STRIDE + bcol[i];
                dB[0] = bR[i].x; dB[1] = bR[i].y; dB[2] = bR[i].z; dB[3] = bR[i].w;
            }
        }
        __syncthreads();
    }

    // ---- epilogue ----
#pragma unroll
    for (int mi = 0; mi < 2; mi++) {
#pragma unroll
        for (int ni = 0; ni < 8; ni++) {
            int r0 = m0 + wm * 32 + mi * 16 + lr;
            int col = wn * 64 + ni * 8 + lc * 2;
#pragma unroll
            for (int half = 0; half < 2; half++) {
                int row = r0 + half * 8;
                float dr = dv[row];
#pragma unroll
                for (int q = 0; q < 2; q++) {
                    float a = acc[mi][ni][half * 2 + q];
                    int c = col + q;
                    float v;
                    if (EPI == 0) {
                        v = a * dr;
                    } else {
                        v = dr * (a + U[(size_t)row * 256 + c]);
                        v = v > 0.0f ? v : 0.0f;
                        if (doDrop)
                            v = drop_apply(v, (unsigned)(row * 256 + c), fk0, fk1);
                    }
                    C[(size_t)row * 256 + c] = v;
                }
            }
        }
    }
}

// --------------------------- aux kernels -----------------------------------
__global__ void deg_kernel(const float *__restrict__ adj)
{
    __shared__ float red[256];
    int row = blockIdx.x;
    const float *a = adj + (size_t)row * NROWS;
    float s = 0.0f;
    for (int j = threadIdx.x; j < NROWS; j += 256) s += __ldcs(&a[j]);
    red[threadIdx.x] = s;
    __syncthreads();
    for (int off = 128; off > 0; off >>= 1) {
        if (threadIdx.x < off) red[threadIdx.x] += red[threadIdx.x + off];
        __syncthreads();
    }
    if (threadIdx.x == 0) g_d[row] = rsqrtf(red[0] + 1.0f);
}

__global__ void pad_x(const float *__restrict__ x)
{
    int idx = blockIdx.x * 256 + threadIdx.x;   // over 8192*512
    int row = idx >> 9, col = idx & 511;
    g_xpad[idx] = (col < 500) ? x[(size_t)row * 500 + col] : 0.0f;
}

__global__ void pad_w(const float *__restrict__ w1)
{
    int idx = blockIdx.x * 256 + threadIdx.x;   // over 512*256
    int row = idx >> 8, col = idx & 255;
    g_wpad[idx] = (row < 500) ? w1[row * 256 + col] : 0.0f;
}

__global__ void out_kernel(const float *__restrict__ Wout,
                           const float *__restrict__ b,
                           float *__restrict__ out)
{
    __shared__ float h[256];
    __shared__ float lg[OUTC];
    __shared__ float s_mx, s_sum;
    int row = blockIdx.x;
    int tid = threadIdx.x;                      // 128 threads
    h[tid] = g_bufH[(size_t)row * 256 + tid];
    h[tid + 128] = g_bufH[(size_t)row * 256 + tid + 128];
    __syncthreads();
    if (tid < OUTC) {
        float s = b[tid];
#pragma unroll 8
        for (int k = 0; k < 256; k++) s += h[k] * Wout[k * OUTC + tid];
        lg[tid] = s;
    }
    __syncthreads();
    if (tid == 0) {
        float m = lg[0];
        for (int i = 1; i < OUTC; i++) m = fmaxf(m, lg[i]);
        float s = 0.0f;
        for (int i = 0; i < OUTC; i++) s += expf(lg[i] - m);
        s_mx = m; s_sum = s;
    }
    __syncthreads();
    if (tid < OUTC)
        out[(size_t)row * OUTC + tid] = expf(lg[tid] - s_mx) / s_sum;
}

// ------------------------------- launch ------------------------------------
extern "C" void kernel_launch(void* const* d_in, const int* in_sizes, int n_in,
                              void* d_out, int out_size)
{
    const float *x    = (const float *)d_in[0];
    const float *adj  = (const float *)d_in[1];
    const float *W1   = (const float *)d_in[2];
    const float *W2   = (const float *)d_in[3];
    const float *W3   = (const float *)d_in[4];
    const float *Wout = (const float *)d_in[5];
    const float *bo   = (const float *)d_in[6];
    float *out = (float *)d_out;

    // JAX dropout keys: base key (0,42); fold_in(layer) = threefry(key,(0,layer))
    unsigned k0a, k1a, k0b, k1b;
    threefry2x32(0u, 42u, 0u, 0u, k0a, k1a);
    threefry2x32(0u, 42u, 0u, 1u, k0b, k1b);

    float *pd, *pxp, *pwp, *pU, *pH;
    cudaGetSymbolAddress((void **)&pd,  g_d);
    cudaGetSymbolAddress((void **)&pxp, g_xpad);
    cudaGetSymbolAddress((void **)&pwp, g_wpad);
    cudaGetSymbolAddress((void **)&pU,  g_bufU);
    cudaGetSymbolAddress((void **)&pH,  g_bufH);

    deg_kernel<<<NROWS, 256>>>(adj);
    pad_x<<<(NROWS * 512) / 256, 256>>>(x);
    pad_w<<<(512 * 256) / 256, 256>>>(W1);

    // Layer 1
    gemm_tf32<0><<<128, 256>>>(pxp, 512, pwp, pU, 512, pd, pd, 0, 0u, 0u);
    gemm_tf32<1><<<128, 256>>>(adj, NROWS, pU, pH, NROWS, pd, pU, 1, k0a, k1a);
    // Layer 2
    gemm_tf32<0><<<128, 256>>>(pH, 256, W2, pU, 256, pd, pd, 0, 0u, 0u);
    gemm_tf32<1><<<128, 256>>>(adj, NROWS, pU, pH, NROWS, pd, pU, 1, k0b, k1b);
    // Layer 3 (no dropout)
    gemm_tf32<0><<<128, 256>>>(pH, 256, W3, pU, 256, pd, pd, 0, 0u, 0u);
    gemm_tf32<1><<<128, 256>>>(adj, NROWS, pU, pH, NROWS, pd, pU, 0, 0u, 0u);

    out_kernel<<<NROWS, 128>>>(Wout, bo, out);
}

// round 5
// speedup vs baseline: 1.8206x; 1.8206x over previous
#include <cuda_runtime.h>
#include <cuda_fp16.h>
#include <cstdint>
#include <math.h>

// ---------------------------------------------------------------------------
// GCN: out = softmax( L3 @ W_out + b ),  L_k = relu(AG @ (L_{k-1} @ W_k)) [*drop]
// AG = D^{-1/2}(A+I)D^{-1/2}.  Refactor: AG @ (H W) = D·(A·U + U), U = D·(H W).
// All GEMMs fp16 (fp32 accum): adjacency converted to half once (fused w/ deg).
// ---------------------------------------------------------------------------

#define NROWS 8192
#define HID   256
#define OUTC  40

// ------------------------------- scratch -----------------------------------
__device__ __half g_adjh[(size_t)NROWS * NROWS];       // 128 MB
__device__ __half g_xpadh[NROWS * 512];
__device__ __half g_w1h[512 * 256];
__device__ __half g_w2h[256 * 256];
__device__ __half g_w3h[256 * 256];
__device__ __half g_bufU[NROWS * HID];
__device__ __half g_bufH[NROWS * HID];
__device__ float  g_d[NROWS];

// ------------------------------ threefry -----------------------------------
__host__ __device__ __forceinline__ void threefry2x32(
    unsigned k0, unsigned k1, unsigned x0, unsigned x1,
    unsigned &o0, unsigned &o1)
{
    unsigned ks2 = k0 ^ k1 ^ 0x1BD11BDAu;
    x0 += k0; x1 += k1;
#define TF_R(r) { x0 += x1; x1 = (x1 << (r)) | (x1 >> (32 - (r))); x1 ^= x0; }
    TF_R(13) TF_R(15) TF_R(26) TF_R(6)
    x0 += k1;  x1 += ks2 + 1u;
    TF_R(17) TF_R(29) TF_R(16) TF_R(24)
    x0 += ks2; x1 += k0 + 2u;
    TF_R(13) TF_R(15) TF_R(26) TF_R(6)
    x0 += k0;  x1 += k1 + 3u;
    TF_R(17) TF_R(29) TF_R(16) TF_R(24)
    x0 += k1;  x1 += ks2 + 4u;
    TF_R(13) TF_R(15) TF_R(26) TF_R(6)
    x0 += ks2; x1 += k0 + 5u;
#undef TF_R
    o0 = x0; o1 = x1;
}

__device__ __forceinline__ float drop_apply(float v, unsigned idx,
                                            unsigned fk0, unsigned fk1)
{
    unsigned o0, o1;
    threefry2x32(fk0, fk1, 0u, idx, o0, o1);   // partitionable path
    unsigned bits = o0 ^ o1;
    float u = __uint_as_float((bits >> 9) | 0x3f800000u) - 1.0f;
    return (u < 0.7f) ? v / 0.7f : 0.0f;
}

// ------------------------------ PTX helpers --------------------------------
__device__ __forceinline__ uint32_t smem_u32(const void *p)
{
    return (uint32_t)__cvta_generic_to_shared(p);
}

__device__ __forceinline__ void cp16(uint32_t dst, const void *src)
{
    asm volatile("cp.async.cg.shared.global [%0], [%1], 16;\n" ::"r"(dst), "l"(src));
}

__device__ __forceinline__ void mma16816(float *c, const uint32_t *a,
                                         uint32_t b0, uint32_t b1)
{
    asm volatile(
        "mma.sync.aligned.m16n8k16.row.col.f32.f16.f16.f32 "
        "{%0,%1,%2,%3}, {%4,%5,%6,%7}, {%8,%9}, {%0,%1,%2,%3};\n"
        : "+f"(c[0]), "+f"(c[1]), "+f"(c[2]), "+f"(c[3])
        : "r"(a[0]), "r"(a[1]), "r"(a[2]), "r"(a[3]), "r"(b0), "r"(b1));
}

// ------------------------------ GEMM core ----------------------------------
// C[8192,256](half) = A[8192,K](half) @ B[K,256](half), fp32 accum.
// Tile 64x256x32, 256 threads (8 warps, 2x4), 4-stage cp.async, ldmatrix.
// EPI==0: C = acc * d[row]
// EPI==1: v = relu(d[row]*(acc + U[row,col])); optional dropout
#define BM 64
#define BN 256
#define BK 32
#define STG 4
#define SA_STRIDE 40            // halves (64B rows + 16B pad)
#define SB_STRIDE 264           // halves
#define SA_TILE (BM * SA_STRIDE)  // 2560
#define SB_TILE (BK * SB_STRIDE)  // 8448
#define SMEM_HALVES (STG * (SA_TILE + SB_TILE))
#define SMEM_BYTES (SMEM_HALVES * 2)   // 88064

template <int EPI>
__global__ void __launch_bounds__(256) gemm_h(
    const __half *__restrict__ A, int lda,
    const __half *__restrict__ B,
    __half *__restrict__ C,
    int K,
    const float *__restrict__ dv,
    const __half *__restrict__ U,
    int doDrop, unsigned fk0, unsigned fk1)
{
    extern __shared__ __half smem[];
    __half *sA = smem;
    __half *sB = smem + STG * SA_TILE;

    const int tid = threadIdx.x;
    const int m0 = blockIdx.x * BM;
    const int warp = tid >> 5, lane = tid & 31;
    const int wm = warp & 1, wn = warp >> 1;  // 2x4 warp grid, warp tile 32x64
    const int lr = lane >> 2, lc = lane & 3;

    // cp.async source/dest index precompute
    const int a_row = tid >> 2, a_chk = (tid & 3) * 8;
    const __half *aSrc = A + (size_t)(m0 + a_row) * lda + a_chk;
    int b_r[4], b_c[4];
#pragma unroll
    for (int i = 0; i < 4; i++) {
        int idx = i * 256 + tid;
        b_r[i] = idx >> 5;
        b_c[i] = (idx & 31) * 8;
    }

    const int KT = K / BK;

    float acc[2][8][4];
#pragma unroll
    for (int mi = 0; mi < 2; mi++)
#pragma unroll
        for (int ni = 0; ni < 8; ni++)
#pragma unroll
            for (int q = 0; q < 4; q++) acc[mi][ni][q] = 0.0f;

    // ---- stage loader ----
    auto load_stage = [&](int kt, int s) {
        uint32_t dA = smem_u32(sA + s * SA_TILE + a_row * SA_STRIDE + a_chk);
        cp16(dA, aSrc + (size_t)kt * BK);
#pragma unroll
        for (int i = 0; i < 4; i++) {
            uint32_t dB = smem_u32(sB + s * SB_TILE + b_r[i] * SB_STRIDE + b_c[i]);
            cp16(dB, B + (size_t)(kt * BK + b_r[i]) * 256 + b_c[i]);
        }
    };

    // prologue: stages 0..STG-2
#pragma unroll
    for (int s = 0; s < STG - 1; s++) {
        load_stage(s, s);
        asm volatile("cp.async.commit_group;\n" ::: "memory");
    }

    for (int kt = 0; kt < KT; kt++) {
        asm volatile("cp.async.wait_group %0;\n" ::"n"(STG - 2) : "memory");
        __syncthreads();

        int nk = kt + STG - 1;
        if (nk < KT) load_stage(nk, nk & (STG - 1));
        asm volatile("cp.async.commit_group;\n" ::: "memory");

        const __half *As = sA + (kt & (STG - 1)) * SA_TILE;
        const __half *Bs = sB + (kt & (STG - 1)) * SB_TILE;

#pragma unroll
        for (int ks = 0; ks < 2; ks++) {
            uint32_t a[2][4], b[4][4];
#pragma unroll
            for (int mi = 0; mi < 2; mi++) {
                uint32_t addr = smem_u32(As + (wm * 32 + mi * 16 + (lane & 15)) * SA_STRIDE
                                         + ks * 16 + (lane >> 4) * 8);
                asm volatile(
                    "ldmatrix.sync.aligned.m8n8.x4.shared.b16 {%0,%1,%2,%3}, [%4];\n"
                    : "=r"(a[mi][0]), "=r"(a[mi][1]), "=r"(a[mi][2]), "=r"(a[mi][3])
                    : "r"(addr));
            }
#pragma unroll
            for (int np = 0; np < 4; np++) {
                uint32_t addr = smem_u32(Bs + (ks * 16 + (lane & 15)) * SB_STRIDE
                                         + wn * 64 + np * 16 + (lane >> 4) * 8);
                asm volatile(
                    "ldmatrix.sync.aligned.m8n8.x4.trans.shared.b16 {%0,%1,%2,%3}, [%4];\n"
                    : "=r"(b[np][0]), "=r"(b[np][1]), "=r"(b[np][2]), "=r"(b[np][3])
                    : "r"(addr));
            }
#pragma unroll
            for (int mi = 0; mi < 2; mi++)
#pragma unroll
                for (int ni = 0; ni < 8; ni++)
                    mma16816(acc[mi][ni], a[mi],
                             b[ni >> 1][(ni & 1) * 2], b[ni >> 1][(ni & 1) * 2 + 1]);
        }
    }

    // ---- epilogue ----
#pragma unroll
    for (int mi = 0; mi < 2; mi++) {
#pragma unroll
        for (int ni = 0; ni < 8; ni++) {
            int r0 = m0 + wm * 32 + mi * 16 + lr;
            int col = wn * 64 + ni * 8 + lc * 2;
#pragma unroll
            for (int h = 0; h < 2; h++) {
                int row = r0 + h * 8;
                float dr = dv[row];
                float v0 = acc[mi][ni][h * 2];
                float v1 = acc[mi][ni][h * 2 + 1];
                if (EPI == 0) {
                    v0 *= dr; v1 *= dr;
                } else {
                    __half2 u = *(const __half2 *)(U + (size_t)row * 256 + col);
                    v0 = dr * (v0 + __half2float(u.x));
                    v1 = dr * (v1 + __half2float(u.y));
                    v0 = fmaxf(v0, 0.0f);
                    v1 = fmaxf(v1, 0.0f);
                    if (doDrop) {
                        v0 = drop_apply(v0, (unsigned)(row * 256 + col), fk0, fk1);
                        v1 = drop_apply(v1, (unsigned)(row * 256 + col + 1), fk0, fk1);
                    }
                }
                *(__half2 *)(C + (size_t)row * 256 + col) = __floats2half2_rn(v0, v1);
            }
        }
    }
}

// --------------------------- prep kernels ----------------------------------
// one block per row: rowsum for degree + fp32 -> fp16 conversion of adjacency
__global__ void prep_adj(const float *__restrict__ adj)
{
    __shared__ float red[256];
    int row = blockIdx.x;
    const float4 *a = (const float4 *)(adj + (size_t)row * NROWS);
    __half2 *o = (__half2 *)(g_adjh + (size_t)row * NROWS);
    float s = 0.0f;
    for (int i = threadIdx.x; i < NROWS / 4; i += 256) {
        float4 v = __ldcs(&a[i]);
        s += (v.x + v.y) + (v.z + v.w);
        o[2 * i]     = __floats2half2_rn(v.x, v.y);
        o[2 * i + 1] = __floats2half2_rn(v.z, v.w);
    }
    red[threadIdx.x] = s;
    __syncthreads();
    for (int off = 128; off > 0; off >>= 1) {
        if (threadIdx.x < off) red[threadIdx.x] += red[threadIdx.x + off];
        __syncthreads();
    }
    if (threadIdx.x == 0) g_d[row] = rsqrtf(red[0] + 1.0f);
}

__global__ void pad_x_h(const float *__restrict__ x)
{
    int idx = blockIdx.x * 256 + threadIdx.x;  // over 8192*512
    int row = idx >> 9, col = idx & 511;
    g_xpadh[idx] = (col < 500) ? __float2half_rn(x[(size_t)row * 500 + col])
                               : __float2half_rn(0.0f);
}

__global__ void pad_w1_h(const float *__restrict__ w1)
{
    int idx = blockIdx.x * 256 + threadIdx.x;  // over 512*256
    int row = idx >> 8, col = idx & 255;
    g_w1h[idx] = (row < 500) ? __float2half_rn(w1[row * 256 + col])
                             : __float2half_rn(0.0f);
}

__global__ void conv_h(const float *__restrict__ src, __half *__restrict__ dst, int n)
{
    int idx = blockIdx.x * 256 + threadIdx.x;
    if (idx < n) dst[idx] = __float2half_rn(src[idx]);
}

// --------------------------- output kernel ---------------------------------
__global__ void out_kernel(const float *__restrict__ Wout,
                           const float *__restrict__ b,
                           float *__restrict__ out)
{
    __shared__ float h[256];
    __shared__ float lg[OUTC];
    __shared__ float s_mx, s_sum;
    int row = blockIdx.x;
    int tid = threadIdx.x;  // 128 threads
    h[tid]       = __half2float(g_bufH[(size_t)row * 256 + tid]);
    h[tid + 128] = __half2float(g_bufH[(size_t)row * 256 + tid + 128]);
    __syncthreads();
    if (tid < OUTC) {
        float s = __ldg(&b[tid]);
#pragma unroll 8
        for (int k = 0; k < 256; k++) s += h[k] * __ldg(&Wout[k * OUTC + tid]);
        lg[tid] = s;
    }
    __syncthreads();
    if (tid == 0) {
        float m = lg[0];
        for (int i = 1; i < OUTC; i++) m = fmaxf(m, lg[i]);
        float s = 0.0f;
        for (int i = 0; i < OUTC; i++) s += expf(lg[i] - m);
        s_mx = m; s_sum = s;
    }
    __syncthreads();
    if (tid < OUTC)
        out[(size_t)row * OUTC + tid] = expf(lg[tid] - s_mx) / s_sum;
}

// ------------------------------- launch ------------------------------------
extern "C" void kernel_launch(void* const* d_in, const int* in_sizes, int n_in,
                              void* d_out, int out_size)
{
    const float *x    = (const float *)d_in[0];
    const float *adj  = (const float *)d_in[1];
    const float *W1   = (const float *)d_in[2];
    const float *W2   = (const float *)d_in[3];
    const float *W3   = (const float *)d_in[4];
    const float *Wout = (const float *)d_in[5];
    const float *bo   = (const float *)d_in[6];
    float *out = (float *)d_out;

    // JAX dropout keys: base key (0,42); fold_in(layer) = threefry(key,(0,layer))
    unsigned k0a, k1a, k0b, k1b;
    threefry2x32(0u, 42u, 0u, 0u, k0a, k1a);
    threefry2x32(0u, 42u, 0u, 1u, k0b, k1b);

    __half *pAdj, *pXp, *pW1, *pW2, *pW3, *pU, *pH;
    float *pd;
    cudaGetSymbolAddress((void **)&pAdj, g_adjh);
    cudaGetSymbolAddress((void **)&pXp,  g_xpadh);
    cudaGetSymbolAddress((void **)&pW1,  g_w1h);
    cudaGetSymbolAddress((void **)&pW2,  g_w2h);
    cudaGetSymbolAddress((void **)&pW3,  g_w3h);
    cudaGetSymbolAddress((void **)&pU,   g_bufU);
    cudaGetSymbolAddress((void **)&pH,   g_bufH);
    cudaGetSymbolAddress((void **)&pd,   g_d);

    cudaFuncSetAttribute(gemm_h<0>, cudaFuncAttributeMaxDynamicSharedMemorySize, SMEM_BYTES);
    cudaFuncSetAttribute(gemm_h<1>, cudaFuncAttributeMaxDynamicSharedMemorySize, SMEM_BYTES);

    prep_adj<<<NROWS, 256>>>(adj);
    pad_x_h<<<(NROWS * 512) / 256, 256>>>(x);
    pad_w1_h<<<(512 * 256) / 256, 256>>>(W1);
    conv_h<<<(256 * 256) / 256, 256>>>(W2, pW2, 256 * 256);
    conv_h<<<(256 * 256) / 256, 256>>>(W3, pW3, 256 * 256);

    // Layer 1
    gemm_h<0><<<128, 256, SMEM_BYTES>>>(pXp, 512, pW1, pU, 512, pd, pU, 0, 0u, 0u);
    gemm_h<1><<<128, 256, SMEM_BYTES>>>(pAdj, NROWS, pU, pH, NROWS, pd, pU, 1, k0a, k1a);
    // Layer 2
    gemm_h<0><<<128, 256, SMEM_BYTES>>>(pH, 256, pW2, pU, 256, pd, pU, 0, 0u, 0u);
    gemm_h<1><<<128, 256, SMEM_BYTES>>>(pAdj, NROWS, pU, pH, NROWS, pd, pU, 1, k0b, k1b);
    // Layer 3 (no dropout)
    gemm_h<0><<<128, 256, SMEM_BYTES>>>(pH, 256, pW3, pU, 256, pd, pU, 0, 0u, 0u);
    gemm_h<1><<<128, 256, SMEM_BYTES>>>(pAdj, NROWS, pU, pH, NROWS, pd, pU, 0, 0u, 0u);

    out_kernel<<<NROWS, 128>>>(Wout, bo, out);
}